// round 7
// baseline (speedup 1.0000x reference)
#include <cuda_runtime.h>

// ---------------------------------------------------------------------------
// DeepGCN fused kernel, round 6.
//  - Graphs independent -> entire 20-layer res+ scan fused, h in registers.
//  - Scatter-add replaced by per-graph 23x23 edge-multiplicity matrix A
//    (agg = A @ z), built once per launch.
//  - Packed fp32 math via PTX fma.rn.f32x2 (double-rate on sm_103a).
//  - NEW: one THREAD per node (253/256 lanes active vs 23/32 before) and
//    ~120 regs/thread -> 16 warps/SM (4/SMSP) for latency hiding.
// ---------------------------------------------------------------------------

static constexpr int NUM_GRAPHS = 16384;
static constexpr int NG        = 23;       // nodes per graph
static constexpr int E_TOTAL   = 4194304;  // total edges
static constexpr int HDIM      = 64;
static constexpr int NLAYERS   = 20;
static constexpr int NB        = 1024;     // clips
static constexpr int NT        = 16;       // window
static constexpr int NC        = 3;        // classes
static constexpr int A_STRIDE  = NG * NG;  // 529

static constexpr int TPB      = 256;       // threads per block
static constexpr int GPB      = 11;        // graphs per block (11*23 = 253)
static constexpr int NODES_PB = GPB * NG;  // 253
static constexpr int ZSTRIDE  = 24;        // z column stride (23 + zero pad)
static constexpr int ZBUF     = HDIM * ZSTRIDE;  // 1536 floats per graph

// Shared layout (floats):
//  [0, 4096)      W_rel  (current layer)
//  [4096, 8192)   W_root (current layer)
//  [8192, 8256)   ln_g
//  [8256, 8320)   ln_b
//  [8320, 8384)   b_rel
//  [8384, 8896)   W_enc
//  [8896, 8960)   b_enc
//  [8960, +GPB*1536) per-graph z buffers (transposed: z[f*24 + node])
static constexpr int SM_FLOATS = 8960 + GPB * ZBUF;
static constexpr int SM_BYTES  = SM_FLOATS * 4;   // 103424 B -> 2 blocks/SM

// Device scratch (allocation-free rule: __device__ globals)
__device__ float g_A[(size_t)NUM_GRAPHS * A_STRIDE];   // ~34.7 MB
__device__ float g_pooled[(size_t)NUM_GRAPHS * HDIM];  // 4 MB

// ---------------------------------------------------------------------------
// f32x2 packed helpers (only reachable via PTX on sm_103a)
// ---------------------------------------------------------------------------
typedef unsigned long long u64t;

__device__ __forceinline__ u64t pk2(float lo, float hi) {
    u64t r;
    asm("mov.b64 %0, {%1, %2};" : "=l"(r) : "f"(lo), "f"(hi));
    return r;
}
__device__ __forceinline__ void upk2(u64t v, float& lo, float& hi) {
    asm("mov.b64 {%0, %1}, %2;" : "=f"(lo), "=f"(hi) : "l"(v));
}
__device__ __forceinline__ u64t fma2(u64t a, u64t b, u64t c) {
    u64t d;
    asm("fma.rn.f32x2 %0, %1, %2, %3;" : "=l"(d) : "l"(a), "l"(b), "l"(c));
    return d;
}
__device__ __forceinline__ u64t add2(u64t a, u64t b) {
    u64t d;
    asm("add.rn.f32x2 %0, %1, %2;" : "=l"(d) : "l"(a), "l"(b));
    return d;
}
__device__ __forceinline__ u64t mul2(u64t a, u64t b) {
    u64t d;
    asm("mul.rn.f32x2 %0, %1, %2;" : "=l"(d) : "l"(a), "l"(b));
    return d;
}

// ---------------------------------------------------------------------------
__global__ void zeroA_kernel() {
    const int n4 = NUM_GRAPHS * A_STRIDE / 4;
    float4* p = reinterpret_cast<float4*>(g_A);
    for (int i = blockIdx.x * blockDim.x + threadIdx.x; i < n4;
         i += gridDim.x * blockDim.x)
        p[i] = make_float4(0.f, 0.f, 0.f, 0.f);
}

__global__ void buildA_kernel(const int* __restrict__ ei) {
    int e = blockIdx.x * blockDim.x + threadIdx.x;
    if (e >= E_TOTAL) return;
    int s = ei[e];            // global src id
    int d = ei[E_TOTAL + e];  // global dst id
    int g  = d / NG;
    int li = d - g * NG;      // local dst
    int lj = s - g * NG;      // local src (same graph by construction)
    atomicAdd(&g_A[(size_t)g * A_STRIDE + li * NG + lj], 1.0f);
}

// ---------------------------------------------------------------------------
// Main fused kernel: encoder + 20 layers + per-graph mean pool.
// One thread per node; block = 11 graphs. h packed f32x2 in registers.
// ---------------------------------------------------------------------------
__global__ void __launch_bounds__(TPB, 2) gcn_main(
    const float* __restrict__ x,
    const float* __restrict__ W_enc, const float* __restrict__ b_enc,
    const float* __restrict__ ln_g,  const float* __restrict__ ln_b,
    const float* __restrict__ W_rel, const float* __restrict__ b_rel,
    const float* __restrict__ W_root)
{
    extern __shared__ float sm[];
    float* wrel_s  = sm;
    float* wroot_s = sm + 4096;
    float* lng_s   = sm + 8192;
    float* lnb_s   = sm + 8256;
    float* brel_s  = sm + 8320;
    float* wenc_s  = sm + 8384;
    float* benc_s  = sm + 8896;
    float* zall    = sm + 8960;

    const int t = threadIdx.x;
    int gl   = t / NG;              // local graph 0..10 (for t<253)
    int node = t - gl * NG;         // local node 0..22
    if (gl >= GPB) { gl = GPB - 1; node = 0; }   // keep pointers in-range
    const int g   = blockIdx.x * GPB + (t / NG);
    const bool act = (t < NODES_PB) && (g < NUM_GRAPHS);
    float* zs = zall + gl * ZBUF;

    // one-time: encoder weights to shared; zero all z buffers (pads stay 0)
    for (int i = t; i < 512; i += TPB) wenc_s[i] = W_enc[i];
    if (t < HDIM) benc_s[t] = b_enc[t];
    for (int i = t; i < GPB * ZBUF; i += TPB) zall[i] = 0.f;
    __syncthreads();

    u64t h2[HDIM / 2];   // packed h (f32x2): 64 regs
    u64t Ap[12];         // packed A row (23 + zero pad): 24 regs

    if (act) {
        // encoder: h = x @ W_enc + b_enc   (x row: 8 floats, 32B aligned)
        const float4* xr = reinterpret_cast<const float4*>(
            x + (size_t)(g * NG + node) * 8);
        float4 xa = xr[0], xb = xr[1];
        float xv[8] = {xa.x, xa.y, xa.z, xa.w, xb.x, xb.y, xb.z, xb.w};
        #pragma unroll
        for (int p = 0; p < HDIM / 2; p++) {
            float v0 = benc_s[2 * p], v1 = benc_s[2 * p + 1];
            #pragma unroll
            for (int k = 0; k < 8; k++) {
                v0 = fmaf(xv[k], wenc_s[k * HDIM + 2 * p],     v0);
                v1 = fmaf(xv[k], wenc_s[k * HDIM + 2 * p + 1], v1);
            }
            h2[p] = pk2(v0, v1);
        }
        // packed A row (constant across layers)
        const float* Ar = g_A + (size_t)g * A_STRIDE + node * NG;
        #pragma unroll
        for (int j = 0; j < 11; j++) Ap[j] = pk2(Ar[2 * j], Ar[2 * j + 1]);
        Ap[11] = pk2(Ar[22], 0.f);   // pad pairs with zeroed z pad entry
    } else {
        #pragma unroll
        for (int p = 0; p < HDIM / 2; p++) h2[p] = 0ull;
        #pragma unroll
        for (int j = 0; j < 12; j++) Ap[j] = 0ull;
    }

    const u64t neg1 = pk2(-1.f, -1.f);

    for (int l = 0; l < NLAYERS; l++) {
        __syncthreads();  // prev layer's weight + z reads complete
        // stage this layer's weights
        {
            const float4* Wr4 = reinterpret_cast<const float4*>(W_rel)  + l * 1024;
            const float4* Wo4 = reinterpret_cast<const float4*>(W_root) + l * 1024;
            float4* dr = reinterpret_cast<float4*>(wrel_s);
            float4* dq = reinterpret_cast<float4*>(wroot_s);
            for (int i = t; i < 1024; i += TPB) { dr[i] = Wr4[i]; dq[i] = Wo4[i]; }
            if (t < HDIM) {
                lng_s[t]  = ln_g[l * HDIM + t];
                lnb_s[t]  = ln_b[l * HDIM + t];
                brel_s[t] = b_rel[l * HDIM + t];
            }
        }
        __syncthreads();

        // z = relu(LayerNorm(h)) -> shared (transposed: z[f*24 + node])
        if (act) {
            const u64t* g8 = reinterpret_cast<const u64t*>(lng_s);
            const u64t* q8 = reinterpret_cast<const u64t*>(lnb_s);
            // mean
            u64t s2 = h2[0];
            #pragma unroll
            for (int p = 1; p < 32; p++) s2 = add2(s2, h2[p]);
            float slo, shi; upk2(s2, slo, shi);
            float mu = (slo + shi) * (1.f / HDIM);
            u64t mu2 = pk2(mu, mu);
            // var
            u64t v2 = 0ull;
            #pragma unroll
            for (int p = 0; p < 32; p++) {
                u64t d = fma2(mu2, neg1, h2[p]);
                v2 = fma2(d, d, v2);
            }
            float vlo, vhi; upk2(v2, vlo, vhi);
            float rs = rsqrtf((vlo + vhi) * (1.f / HDIM) + 1e-5f);
            u64t rs2 = pk2(rs, rs);
            // z -> shared
            #pragma unroll
            for (int p = 0; p < 32; p++) {
                u64t d  = fma2(mu2, neg1, h2[p]);
                u64t m  = mul2(d, rs2);
                u64t zz = fma2(m, g8[p], q8[p]);
                float zlo, zhi; upk2(zz, zlo, zhi);
                zs[(2 * p)     * ZSTRIDE + node] = fmaxf(zlo, 0.f);
                zs[(2 * p + 1) * ZSTRIDE + node] = fmaxf(zhi, 0.f);
            }
        }
        __syncthreads();   // z visible to all nodes of the graph

        // h += b_rel + (A@z) @ W_rel + z @ W_root     (packed f32x2)
        if (act) {
            const u64t* br8 = reinterpret_cast<const u64t*>(brel_s);
            #pragma unroll
            for (int p = 0; p < 32; p++) h2[p] = add2(h2[p], br8[p]);

            #pragma unroll 2
            for (int k = 0; k < HDIM; k++) {
                const float* zc = zs + k * ZSTRIDE;       // column k (24 floats)
                const ulonglong2* z2 = reinterpret_cast<const ulonglong2*>(zc);

                // agg[node][k] = Arow . z(:,k) — two chains of 6 FMA2
                u64t acc0 = 0ull, acc1 = 0ull;
                #pragma unroll
                for (int j = 0; j < 3; j++) {
                    ulonglong2 za = z2[2 * j];
                    ulonglong2 zb = z2[2 * j + 1];
                    acc0 = fma2(Ap[4 * j],     za.x, acc0);
                    acc1 = fma2(Ap[4 * j + 1], za.y, acc1);
                    acc0 = fma2(Ap[4 * j + 2], zb.x, acc0);
                    acc1 = fma2(Ap[4 * j + 3], zb.y, acc1);
                }
                u64t accs = add2(acc0, acc1);
                float alo, ahi; upk2(accs, alo, ahi);
                float av = alo + ahi;
                u64t a2  = pk2(av, av);
                float zk = zc[node];
                u64t zk2 = pk2(zk, zk);

                const ulonglong2* wr2 =
                    reinterpret_cast<const ulonglong2*>(wrel_s + k * HDIM);
                const ulonglong2* wo2 =
                    reinterpret_cast<const ulonglong2*>(wroot_s + k * HDIM);
                #pragma unroll
                for (int q = 0; q < 16; q++) {
                    ulonglong2 w1 = wr2[q];
                    ulonglong2 w2 = wo2[q];
                    h2[2 * q]     = fma2(a2, w1.x, fma2(zk2, w2.x, h2[2 * q]));
                    h2[2 * q + 1] = fma2(a2, w1.y, fma2(zk2, w2.y, h2[2 * q + 1]));
                }
            }
        }
    }

    // per-graph mean pool (reuse z buffers to stage h)
    __syncthreads();
    if (act) {
        #pragma unroll
        for (int p = 0; p < 32; p++) {
            float lo, hi;
            upk2(h2[p], lo, hi);
            zs[(2 * p)     * ZSTRIDE + node] = lo;
            zs[(2 * p + 1) * ZSTRIDE + node] = hi;
        }
    }
    __syncthreads();
    for (int idx = t; idx < GPB * HDIM; idx += TPB) {
        int gg = idx / HDIM;              // local graph
        int f  = idx - gg * HDIM;
        int gout = blockIdx.x * GPB + gg;
        if (gout < NUM_GRAPHS) {
            const float* zb = zall + gg * ZBUF + f * ZSTRIDE;
            float s = 0.f;
            #pragma unroll
            for (int i = 0; i < NG; i++) s += zb[i];
            g_pooled[(size_t)gout * HDIM + f] = s * (1.f / NG);
        }
    }
}

// ---------------------------------------------------------------------------
// Head: xt = pooled.reshape(B,T,H)+pos; v = mean_t; out = relu(v@W1+b1)@W2+b2
// ---------------------------------------------------------------------------
__global__ void head_kernel(const float* __restrict__ pos,
                            const float* __restrict__ W1, const float* __restrict__ b1,
                            const float* __restrict__ W2, const float* __restrict__ b2,
                            float* __restrict__ out)
{
    __shared__ float vs[HDIM];
    __shared__ float h1s[HDIM];
    const int b = blockIdx.x;
    const int f = threadIdx.x;

    float v = 0.f;
    #pragma unroll
    for (int tt = 0; tt < NT; tt++)
        v += g_pooled[(size_t)(b * NT + tt) * HDIM + f] + pos[tt * HDIM + f];
    vs[f] = v * (1.f / NT);
    __syncthreads();

    float acc = b1[f];
    #pragma unroll
    for (int k = 0; k < HDIM; k++) acc = fmaf(vs[k], W1[k * HDIM + f], acc);
    h1s[f] = fmaxf(acc, 0.f);
    __syncthreads();

    if (f < NC) {
        float o = b2[f];
        #pragma unroll
        for (int k = 0; k < HDIM; k++) o = fmaf(h1s[k], W2[k * NC + f], o);
        out[b * NC + f] = o;
    }
}

// ---------------------------------------------------------------------------
extern "C" void kernel_launch(void* const* d_in, const int* in_sizes, int n_in,
                              void* d_out, int out_size)
{
    const float* x     = (const float*)d_in[0];
    const int*   ei    = (const int*)  d_in[1];
    // d_in[2] = batch (unused: graphs are contiguous blocks of 23 nodes)
    const float* W_enc = (const float*)d_in[3];
    const float* b_enc = (const float*)d_in[4];
    const float* ln_g  = (const float*)d_in[5];
    const float* ln_b  = (const float*)d_in[6];
    const float* W_rel = (const float*)d_in[7];
    const float* b_rel = (const float*)d_in[8];
    const float* W_root= (const float*)d_in[9];
    const float* pos   = (const float*)d_in[10];
    const float* W1    = (const float*)d_in[11];
    const float* b1    = (const float*)d_in[12];
    const float* W2    = (const float*)d_in[13];
    const float* b2    = (const float*)d_in[14];
    float* out = (float*)d_out;

    (void)in_sizes; (void)n_in; (void)out_size;

    cudaFuncSetAttribute(gcn_main, cudaFuncAttributeMaxDynamicSharedMemorySize,
                         SM_BYTES);

    zeroA_kernel<<<1024, 256>>>();
    buildA_kernel<<<(E_TOTAL + 255) / 256, 256>>>(ei);
    const int grid = (NUM_GRAPHS + GPB - 1) / GPB;   // 1490
    gcn_main<<<grid, TPB, SM_BYTES>>>(
        x, W_enc, b_enc, ln_g, ln_b, W_rel, b_rel, W_root);
    head_kernel<<<NB, HDIM>>>(pos, W1, b1, W2, b2, out);
}